// round 5
// baseline (speedup 1.0000x reference)
#include <cuda_runtime.h>
#include <math.h>

#define NB    4
#define NPER  100000
#define NSOLS 8

// Global accumulators (doubles for accurate, order-insensitive-enough reduction).
__device__ double g_energy[NB * NSOLS];
__device__ double g_load[NB * NSOLS];
__device__ double g_vol[NB];

// ---------------------------------------------------------------------------
// Kernel 1: zero accumulators
// ---------------------------------------------------------------------------
__global__ void k_zero() {
    int t = threadIdx.x;
    if (t < NB * NSOLS) {
        g_energy[t] = 0.0;
        g_load[t]   = 0.0;
    }
    if (t < NB) g_vol[t] = 0.0;
}

// ---------------------------------------------------------------------------
// Kernel 2: load[b][s] = sum_n mass*rhs*x ; vol[b] = sum_n mass
// grid = (ceil(NPER/1024), NB), block = 256, 4 rows/thread
// ---------------------------------------------------------------------------
__global__ void k_loadvol(const float* __restrict__ x,
                          const float* __restrict__ rhs,
                          const float* __restrict__ mass) {
    const int b    = blockIdx.y;
    const int base = blockIdx.x * 1024 + threadIdx.x;

    float accL[NSOLS];
#pragma unroll
    for (int s = 0; s < NSOLS; s++) accL[s] = 0.0f;
    float accV = 0.0f;

    const float4* x4 = (const float4*)x;
    const float4* r4 = (const float4*)rhs;

#pragma unroll
    for (int k = 0; k < 4; k++) {
        int n = base + k * 256;
        if (n < NPER) {
            int idx = b * NPER + n;
            float m = mass[idx];
            float4 xa = x4[idx * 2], xb = x4[idx * 2 + 1];
            float4 ra = r4[idx * 2], rb = r4[idx * 2 + 1];
            accV    += m;
            accL[0] += m * ra.x * xa.x;
            accL[1] += m * ra.y * xa.y;
            accL[2] += m * ra.z * xa.z;
            accL[3] += m * ra.w * xa.w;
            accL[4] += m * rb.x * xb.x;
            accL[5] += m * rb.y * xb.y;
            accL[6] += m * rb.z * xb.z;
            accL[7] += m * rb.w * xb.w;
        }
    }

    // full-warp butterfly reduction of 9 values
#pragma unroll
    for (int off = 16; off >= 1; off >>= 1) {
#pragma unroll
        for (int s = 0; s < NSOLS; s++)
            accL[s] += __shfl_xor_sync(0xffffffffu, accL[s], off);
        accV += __shfl_xor_sync(0xffffffffu, accV, off);
    }

    if ((threadIdx.x & 31) == 0) {
#pragma unroll
        for (int s = 0; s < NSOLS; s++)
            atomicAdd(&g_load[b * NSOLS + s], (double)accL[s]);
        atomicAdd(&g_vol[b], (double)accV);
    }
}

// ---------------------------------------------------------------------------
// Kernel 3: a_energy[b][s] = sum_nnz val * x[col][s] * x[row][s], b = row/NPER
// Indices are INT32 (JAX x64 disabled demotes the "int64" array).
// Lane-pair decomposition: even lane handles s=0..3, odd lane s=4..7 of the
// same nnz, so each gather LDG covers 16 nnz with 16 distinct 128B lines
// (2 wavefronts/nnz — structural minimum for unsorted random gathers).
// Index/val loads are duplicated across the lane pair but warp-coalesce to a
// single 128B line per load — no extra traffic.
// ---------------------------------------------------------------------------
__global__ void k_energy(const float* __restrict__ x,
                         const int* __restrict__ rows,
                         const int* __restrict__ cols,
                         const float* __restrict__ vals,
                         int nnz) {
    __shared__ double s_e[NB * NSOLS];

    const int tid   = threadIdx.x;
    const int gtid  = blockIdx.x * blockDim.x + tid;
    const int half  = gtid & 1;                      // 0: s=0..3, 1: s=4..7
    const int pair0 = gtid >> 1;
    const int pstep = (gridDim.x * blockDim.x) >> 1;

    const float4* x4 = (const float4*)x;

    float acc[NB][4];
#pragma unroll
    for (int bb = 0; bb < NB; bb++)
#pragma unroll
        for (int j = 0; j < 4; j++) acc[bb][j] = 0.0f;

    if (tid < NB * NSOLS) s_e[tid] = 0.0;
    __syncthreads();

    for (int i = pair0; i < nnz; i += pstep) {
        unsigned r = (unsigned)__ldcs(&rows[i]);     // streaming, no reuse
        unsigned c = (unsigned)__ldcs(&cols[i]);
        float    v = __ldcs(&vals[i]);

        float4 xr = __ldg(&x4[r * 2u + (unsigned)half]);
        float4 xc = __ldg(&x4[c * 2u + (unsigned)half]);

        int b = (int)(r / (unsigned)NPER);           // batch of this nnz

        float t0 = v * xr.x * xc.x;
        float t1 = v * xr.y * xc.y;
        float t2 = v * xr.z * xc.z;
        float t3 = v * xr.w * xc.w;

#pragma unroll
        for (int bb = 0; bb < NB; bb++) {
            if (bb == b) {
                acc[bb][0] += t0;
                acc[bb][1] += t1;
                acc[bb][2] += t2;
                acc[bb][3] += t3;
            }
        }
    }

    // butterfly over lanes of same half (xor masks keep bit0 fixed)
#pragma unroll
    for (int off = 2; off < 32; off <<= 1) {
#pragma unroll
        for (int bb = 0; bb < NB; bb++)
#pragma unroll
            for (int j = 0; j < 4; j++)
                acc[bb][j] += __shfl_xor_sync(0xffffffffu, acc[bb][j], off);
    }

    // lanes 0 and 1 hold warp totals for their s-half
    if ((tid & 31) < 2) {
#pragma unroll
        for (int bb = 0; bb < NB; bb++)
#pragma unroll
            for (int j = 0; j < 4; j++)
                atomicAdd(&s_e[bb * NSOLS + half * 4 + j], (double)acc[bb][j]);
    }
    __syncthreads();

    if (tid < NB * NSOLS) atomicAdd(&g_energy[tid], s_e[tid]);
}

// ---------------------------------------------------------------------------
// Kernel 4: scalar epilogue
// ---------------------------------------------------------------------------
__global__ void k_final(float* __restrict__ out) {
    if (threadIdx.x == 0) {
        double kkt = 0.0, comp = 0.0;
        for (int b = 0; b < NB; b++) {
            double vol = g_vol[b];
            for (int s = 0; s < NSOLS; s++) {
                double a = g_energy[b * NSOLS + s];
                double L = g_load[b * NSOLS + s];
                double sigma = L / fmax(a, 1e-4);
                kkt  += (0.5 * a * sigma - L) * sigma / vol;
                comp += sigma * L / vol;
            }
        }
        kkt  /= (double)(NB * NSOLS);
        comp  = -comp / (double)(NB * NSOLS);
        // w_compliance = LAMB_COMP = 0.5, w_kkt = 0.5
        out[0] = (float)(0.5 * comp + 0.5 * kkt);
    }
}

// ---------------------------------------------------------------------------
// Launch
// inputs (metadata order): x_hat, rhs, A_ind(int32!), A_val, subspace(unused), mass
// ---------------------------------------------------------------------------
extern "C" void kernel_launch(void* const* d_in, const int* in_sizes, int n_in,
                              void* d_out, int out_size) {
    const float* x_hat = (const float*)d_in[0];
    const float* rhs   = (const float*)d_in[1];
    const int*   A_ind = (const int*)d_in[2];
    const float* A_val = (const float*)d_in[3];
    const float* mass  = (const float*)d_in[5];

    int nnz = in_sizes[3];                 // element count of A_val
    const int* rows = A_ind;               // A_ind[0, :]
    const int* cols = A_ind + nnz;         // A_ind[1, :]

    k_zero<<<1, 64>>>();

    dim3 glv((NPER + 1023) / 1024, NB);
    k_loadvol<<<glv, 256>>>(x_hat, rhs, mass);

    k_energy<<<1184, 256>>>(x_hat, rows, cols, A_val, nnz);

    k_final<<<1, 32>>>((float*)d_out);
}

// round 6
// speedup vs baseline: 1.6069x; 1.6069x over previous
#include <cuda_runtime.h>
#include <math.h>

#define NB      4
#define NPER    100000
#define NSOLS   8
#define EBLOCKS 1184          // k_energy grid size (8 CTAs * 148 SMs)
#define LBLOCKS 98            // ceil(NPER/1024)

// Per-block partial sums (overwritten every call — no zeroing kernel needed).
// Layouts are column-major per accumulator so k_final reads coalesced runs.
__device__ double g_epart[NB * NSOLS * EBLOCKS];   // [32][EBLOCKS]
__device__ double g_lpart[NB * NSOLS * LBLOCKS];   // [32][LBLOCKS]
__device__ double g_vpart[NB * LBLOCKS];           // [4][LBLOCKS]

// ---------------------------------------------------------------------------
// Kernel 1: load[b][s] = sum_n mass*rhs*x ; vol[b] = sum_n mass
// grid = (LBLOCKS, NB), block = 256, 4 rows/thread
// ---------------------------------------------------------------------------
__global__ void k_loadvol(const float* __restrict__ x,
                          const float* __restrict__ rhs,
                          const float* __restrict__ mass) {
    __shared__ double s_l[NSOLS];
    __shared__ double s_v;

    const int tid  = threadIdx.x;
    const int lane = tid & 31;
    const int b    = blockIdx.y;
    const int base = blockIdx.x * 1024 + tid;

    if (tid < NSOLS) s_l[tid] = 0.0;
    if (tid == NSOLS) s_v = 0.0;
    __syncthreads();

    float accL[NSOLS];
#pragma unroll
    for (int s = 0; s < NSOLS; s++) accL[s] = 0.0f;
    float accV = 0.0f;

    const float4* x4 = (const float4*)x;
    const float4* r4 = (const float4*)rhs;

#pragma unroll
    for (int k = 0; k < 4; k++) {
        int n = base + k * 256;
        if (n < NPER) {
            int idx = b * NPER + n;
            float m = mass[idx];
            float4 xa = x4[idx * 2], xb = x4[idx * 2 + 1];
            float4 ra = r4[idx * 2], rb = r4[idx * 2 + 1];
            accV    += m;
            accL[0] += m * ra.x * xa.x;
            accL[1] += m * ra.y * xa.y;
            accL[2] += m * ra.z * xa.z;
            accL[3] += m * ra.w * xa.w;
            accL[4] += m * rb.x * xb.x;
            accL[5] += m * rb.y * xb.y;
            accL[6] += m * rb.z * xb.z;
            accL[7] += m * rb.w * xb.w;
        }
    }

#pragma unroll
    for (int off = 16; off >= 1; off >>= 1) {
#pragma unroll
        for (int s = 0; s < NSOLS; s++)
            accL[s] += __shfl_xor_sync(0xffffffffu, accL[s], off);
        accV += __shfl_xor_sync(0xffffffffu, accV, off);
    }

    if (lane == 0) {
#pragma unroll
        for (int s = 0; s < NSOLS; s++)
            atomicAdd(&s_l[s], (double)accL[s]);
        atomicAdd(&s_v, (double)accV);
    }
    __syncthreads();

    if (tid < NSOLS)
        g_lpart[(b * NSOLS + tid) * LBLOCKS + blockIdx.x] = s_l[tid];
    if (tid == NSOLS)
        g_vpart[b * LBLOCKS + blockIdx.x] = s_v;
}

// ---------------------------------------------------------------------------
// Kernel 2: a_energy[b][s] = sum_nnz val * x[col][s] * x[row][s], b = row/NPER
// 4-lane split: lane quad handles one nnz; lane ql loads float2 covering
// s = 2*ql, 2*ql+1. One LDG.64 gather covers 8 nnz -> 8 distinct random lines,
// halving the per-instruction replay chain vs the 16-line LDG.128 variant so
// the l1tex queue can interleave wavefronts across LDGs (2.07 -> ~1.0 cyc/wf).
// Index/val loads replicate x4 across the quad but coalesce to one 32B sector.
// ---------------------------------------------------------------------------
__global__ void k_energy(const float* __restrict__ x,
                         const int* __restrict__ rows,
                         const int* __restrict__ cols,
                         const float* __restrict__ vals,
                         int nnz) {
    __shared__ double s_e[NB * NSOLS];

    const int tid   = threadIdx.x;
    const int lane  = tid & 31;
    const int gtid  = blockIdx.x * blockDim.x + tid;
    const int ql    = gtid & 3;                   // quad lane: s-pair index
    const int quad  = gtid >> 2;                  // nnz index start
    const int qstep = (gridDim.x * blockDim.x) >> 2;

    const float2* x2 = (const float2*)x;

    float acc[NB][2];
#pragma unroll
    for (int bb = 0; bb < NB; bb++) {
        acc[bb][0] = 0.0f;
        acc[bb][1] = 0.0f;
    }

    if (tid < NB * NSOLS) s_e[tid] = 0.0;
    __syncthreads();

    for (int i = quad; i < nnz; i += qstep) {
        unsigned r = (unsigned)__ldcs(&rows[i]);  // streaming, no reuse
        unsigned c = (unsigned)__ldcs(&cols[i]);
        float    v = __ldcs(&vals[i]);

        float2 xr = __ldg(&x2[r * 4u + (unsigned)ql]);
        float2 xc = __ldg(&x2[c * 4u + (unsigned)ql]);

        int b = (int)(r / (unsigned)NPER);

        float t0 = v * xr.x * xc.x;
        float t1 = v * xr.y * xc.y;

#pragma unroll
        for (int bb = 0; bb < NB; bb++) {
            if (bb == b) {
                acc[bb][0] += t0;
                acc[bb][1] += t1;
            }
        }
    }

    // butterfly over the 8 quads of the warp (xor 4,8,16 keeps ql fixed)
#pragma unroll
    for (int off = 4; off < 32; off <<= 1) {
#pragma unroll
        for (int bb = 0; bb < NB; bb++) {
            acc[bb][0] += __shfl_xor_sync(0xffffffffu, acc[bb][0], off);
            acc[bb][1] += __shfl_xor_sync(0xffffffffu, acc[bb][1], off);
        }
    }

    // lanes 0..3 hold warp totals for s-pair ql
    if (lane < 4) {
#pragma unroll
        for (int bb = 0; bb < NB; bb++) {
            atomicAdd(&s_e[bb * NSOLS + lane * 2 + 0], (double)acc[bb][0]);
            atomicAdd(&s_e[bb * NSOLS + lane * 2 + 1], (double)acc[bb][1]);
        }
    }
    __syncthreads();

    if (tid < NB * NSOLS)
        g_epart[tid * EBLOCKS + blockIdx.x] = s_e[tid];
}

// ---------------------------------------------------------------------------
// Kernel 3: reduce partials + scalar epilogue. 1 block, 1024 threads.
// Warp w reduces energy column w (EBLOCKS entries, coalesced) and load
// column w (LBLOCKS entries); warps 0..3 also reduce vol. Then 32 threads
// compute the per-(b,s) epilogue (divides in parallel) and butterfly-sum.
// ---------------------------------------------------------------------------
__global__ void k_final(float* __restrict__ out) {
    __shared__ double sh_e[NB * NSOLS];
    __shared__ double sh_l[NB * NSOLS];
    __shared__ double sh_v[NB];

    const int tid  = threadIdx.x;
    const int w    = tid >> 5;
    const int lane = tid & 31;

    double e = 0.0, l = 0.0, vv = 0.0;
    for (int i = lane; i < EBLOCKS; i += 32) e += g_epart[w * EBLOCKS + i];
    for (int i = lane; i < LBLOCKS; i += 32) l += g_lpart[w * LBLOCKS + i];
    if (w < NB)
        for (int i = lane; i < LBLOCKS; i += 32) vv += g_vpart[w * LBLOCKS + i];

#pragma unroll
    for (int off = 16; off >= 1; off >>= 1) {
        e  += __shfl_xor_sync(0xffffffffu, e, off);
        l  += __shfl_xor_sync(0xffffffffu, l, off);
        vv += __shfl_xor_sync(0xffffffffu, vv, off);
    }

    if (lane == 0) {
        sh_e[w] = e;
        sh_l[w] = l;
        if (w < NB) sh_v[w] = vv;
    }
    __syncthreads();

    if (w == 0) {
        // lane = b*8 + s
        double a   = sh_e[lane];
        double L   = sh_l[lane];
        double vol = sh_v[lane >> 3];

        double sigma = L / fmax(a, 1e-4);
        double kkt_e = (0.5 * a * sigma - L) * sigma / vol;
        double cmp_b = sigma * L / vol;
        // result = 0.5*mean(kkt_e) + 0.5*(-mean(cmp_b)); mean over 32 terms
        double contrib = (0.5 * kkt_e - 0.5 * cmp_b) * (1.0 / 32.0);

#pragma unroll
        for (int off = 16; off >= 1; off >>= 1)
            contrib += __shfl_xor_sync(0xffffffffu, contrib, off);

        if (lane == 0) out[0] = (float)contrib;
    }
}

// ---------------------------------------------------------------------------
// Launch
// inputs (metadata order): x_hat, rhs, A_ind(int32), A_val, subspace(unused), mass
// ---------------------------------------------------------------------------
extern "C" void kernel_launch(void* const* d_in, const int* in_sizes, int n_in,
                              void* d_out, int out_size) {
    const float* x_hat = (const float*)d_in[0];
    const float* rhs   = (const float*)d_in[1];
    const int*   A_ind = (const int*)d_in[2];
    const float* A_val = (const float*)d_in[3];
    const float* mass  = (const float*)d_in[5];

    int nnz = in_sizes[3];
    const int* rows = A_ind;          // A_ind[0, :]
    const int* cols = A_ind + nnz;    // A_ind[1, :]

    dim3 glv(LBLOCKS, NB);
    k_loadvol<<<glv, 256>>>(x_hat, rhs, mass);

    k_energy<<<EBLOCKS, 256>>>(x_hat, rows, cols, A_val, nnz);

    k_final<<<1, 1024>>>((float*)d_out);
}